// round 8
// baseline (speedup 1.0000x reference)
#include <cuda_runtime.h>
#include <cstdint>

// LIF recurrence: T=64 steps, B*N = 524288 independent lanes.
//   h = v + (x - v) * 0.5 ; s = (h>=1) ; v = s ? 0 : h
// Pure HBM stream: 134 MB in + 134 MB out. Harness has been pinned at
// ~47.5us (5.65 TB/s sustained) across 4 structurally different kernels.
// R8: DRAM bus-turnaround batching. 8-timestep body:
//   8x LDG.128 burst (loads independent of v) -> compute chain -> 8x STG.128
// burst. Output reuses the load buffer (regs ~48). 128-thr blocks keep
// R6's 1024-CTA even balance; no cross-body register rotation.

static constexpr int T = 64;
static constexpr int STEPS = 8;   // timesteps per body

__global__ void __launch_bounds__(128) lif_kernel(const float4* __restrict__ x,
                                                  float4* __restrict__ out,
                                                  int lanes4)  // B*N/4 per timestep
{
    int i = blockIdx.x * blockDim.x + threadIdx.x;
    if (i >= lanes4) return;

    float4 v = make_float4(0.f, 0.f, 0.f, 0.f);

    for (int t = 0; t < T; t += STEPS) {
        float4 buf[STEPS];

        // read burst: 8 independent LDG.128
        #pragma unroll
        for (int d = 0; d < STEPS; ++d)
            buf[d] = x[(size_t)(t + d) * lanes4 + i];

        // compute chain (serial in t, cheap); overwrite buf with spikes
        #pragma unroll
        for (int d = 0; d < STEPS; ++d) {
            float4 xt = buf[d];
            float4 h, s;
            h.x = v.x + (xt.x - v.x) * 0.5f;
            h.y = v.y + (xt.y - v.y) * 0.5f;
            h.z = v.z + (xt.z - v.z) * 0.5f;
            h.w = v.w + (xt.w - v.w) * 0.5f;

            s.x = (h.x >= 1.0f) ? 1.0f : 0.0f;
            s.y = (h.y >= 1.0f) ? 1.0f : 0.0f;
            s.z = (h.z >= 1.0f) ? 1.0f : 0.0f;
            s.w = (h.w >= 1.0f) ? 1.0f : 0.0f;

            v.x = (h.x >= 1.0f) ? 0.0f : h.x;
            v.y = (h.y >= 1.0f) ? 0.0f : h.y;
            v.z = (h.z >= 1.0f) ? 0.0f : h.z;
            v.w = (h.w >= 1.0f) ? 0.0f : h.w;

            buf[d] = s;
        }

        // write burst: 8 back-to-back STG.128
        #pragma unroll
        for (int d = 0; d < STEPS; ++d)
            out[(size_t)(t + d) * lanes4 + i] = buf[d];
    }
}

extern "C" void kernel_launch(void* const* d_in, const int* in_sizes, int n_in,
                              void* d_out, int out_size)
{
    const float4* x = (const float4*)d_in[0];
    float4* out = (float4*)d_out;

    int total = in_sizes[0];          // T * B * N
    int lanes = total / T;            // 524288
    int lanes4 = lanes / 4;           // 131072

    int threads = 128;                // 1024 CTAs -> even per-SM balance
    int blocks = (lanes4 + threads - 1) / threads;
    lif_kernel<<<blocks, threads>>>(x, out, lanes4);
}